// round 2
// baseline (speedup 1.0000x reference)
#include <cuda_runtime.h>
#include <cuda_bf16.h>

// LePE CSWin attention, shapes fixed: B=4, C=64, H=W=128, heads=8, hd=8, SPLIT=2.
// Windows: 128x2 column strips -> 64 windows per batch image, N=256 tokens/window.
// One CTA per (window, head): 256 threads, one per query token.
// Softmax without max-subtraction (logits ~ N(0,1); clamp guards overflow).
// LePE = per-window depthwise 3x3 conv on V, computed from the smem V tile.

#define HGT 128
#define WID 128
#define HW  (HGT*WID)
#define NT  256           // tokens per window
#define HD  8             // head dim

__global__ __launch_bounds__(256, 4)
void lepe_attn_kernel(const float* __restrict__ temp,
                      const float* __restrict__ conv_w,
                      const float* __restrict__ conv_b,
                      float* __restrict__ out)
{
    const int wcol = blockIdx.x;   // 0..63  (which column-pair window)
    const int b    = blockIdx.y;   // 0..3
    const int head = blockIdx.z;   // 0..7

    const int n = threadIdx.x;     // 0..255 token within window
    const int h = n >> 1;
    const int j = n & 1;

    __shared__ float Ks[NT][HD];
    __shared__ float Vs[NT][HD];
    __shared__ float wsh[HD][9];
    __shared__ float bsh[HD];

    const int c0 = head * HD;
    const int w0 = 2 * wcol;

    // temp[b, plane, c, h, w]  index = ((b*3 + plane)*64 + c)*HW + h*WID + w
    const size_t baseQ = ((size_t)(b * 3 + 0) * 64 + c0) * HW + (size_t)h * WID + w0 + j;
    const size_t baseK = ((size_t)(b * 3 + 1) * 64 + c0) * HW + (size_t)h * WID + w0 + j;
    const size_t baseV = ((size_t)(b * 3 + 2) * 64 + c0) * HW + (size_t)h * WID + w0 + j;

    // Stage K, V for this (window, head) into smem. Each thread owns one token row.
#pragma unroll
    for (int d = 0; d < HD; ++d) {
        Ks[n][d] = temp[baseK + (size_t)d * HW];
        Vs[n][d] = temp[baseV + (size_t)d * HW];
    }
    if (threadIdx.x < 72) {
        int d = threadIdx.x / 9, i = threadIdx.x % 9;
        wsh[d][i] = conv_w[(c0 + d) * 9 + i];
    }
    if (threadIdx.x < 8) bsh[threadIdx.x] = conv_b[c0 + threadIdx.x];

    // q row in registers; fold scale (hd^-0.5) and log2(e) for exp2f.
    const float sc = 0.35355339059327373f * 1.4426950408889634f;
    float q[HD];
#pragma unroll
    for (int d = 0; d < HD; ++d) q[d] = temp[baseQ + (size_t)d * HW] * sc;

    __syncthreads();

    float o[HD] = {0.f, 0.f, 0.f, 0.f, 0.f, 0.f, 0.f, 0.f};
    float l = 0.f;

#pragma unroll 4
    for (int m = 0; m < NT; ++m) {
        const float4 k0 = *(const float4*)&Ks[m][0];
        const float4 k1 = *(const float4*)&Ks[m][4];
        // split the dot into two chains for ILP
        float sA = q[0] * k0.x + q[1] * k0.y;
        float sB = q[2] * k0.z + q[3] * k0.w;
        sA += q[4] * k1.x; sB += q[5] * k1.y;
        sA += q[6] * k1.z; sB += q[7] * k1.w;
        float s = sA + sB;
        // exact softmax numerator (no max subtraction); clamp only as overflow guard
        float p = exp2f(fminf(s, 100.f));
        l += p;
        const float4 v0 = *(const float4*)&Vs[m][0];
        const float4 v1 = *(const float4*)&Vs[m][4];
        o[0] += p * v0.x; o[1] += p * v0.y; o[2] += p * v0.z; o[3] += p * v0.w;
        o[4] += p * v1.x; o[5] += p * v1.y; o[6] += p * v1.z; o[7] += p * v1.w;
    }

    const float inv = 1.0f / l;

    // LePE: depthwise 3x3 conv on the V window (within-window SAME padding).
    float r[HD];
#pragma unroll
    for (int d = 0; d < HD; ++d) r[d] = bsh[d];

#pragma unroll
    for (int dy = -1; dy <= 1; ++dy) {
        const int hh = h + dy;
        if (hh < 0 || hh >= HGT) continue;
#pragma unroll
        for (int dx = -1; dx <= 1; ++dx) {
            const int jj = j + dx;
            if (jj < 0 || jj > 1) continue;
            const int mm = hh * 2 + jj;
            const int wi = (dy + 1) * 3 + (dx + 1);
#pragma unroll
            for (int d = 0; d < HD; ++d) r[d] += Vs[mm][d] * wsh[d][wi];
        }
    }

    // out[b, h*W + w, c0 + d]
    const size_t oidx = ((size_t)b * (HGT * WID) + (size_t)h * WID + w0 + j) * 64 + c0;
    float4 r0, r1;
    r0.x = o[0] * inv + r[0]; r0.y = o[1] * inv + r[1];
    r0.z = o[2] * inv + r[2]; r0.w = o[3] * inv + r[3];
    r1.x = o[4] * inv + r[4]; r1.y = o[5] * inv + r[5];
    r1.z = o[6] * inv + r[6]; r1.w = o[7] * inv + r[7];
    *(float4*)&out[oidx]     = r0;
    *(float4*)&out[oidx + 4] = r1;
}

extern "C" void kernel_launch(void* const* d_in, const int* in_sizes, int n_in,
                              void* d_out, int out_size)
{
    const float* temp   = (const float*)d_in[0];
    const float* conv_w = (const float*)d_in[1];
    const float* conv_b = (const float*)d_in[2];
    float* out          = (float*)d_out;

    dim3 grid(64, 4, 8);   // (wcol, b, head)
    dim3 block(256);
    lepe_attn_kernel<<<grid, block>>>(temp, conv_w, conv_b, out);
}

// round 4
// speedup vs baseline: 1.4174x; 1.4174x over previous
#include <cuda_runtime.h>
#include <cuda_bf16.h>

// LePE CSWin attention: B=4, C=64, H=W=128, heads=8, hd=8, SPLIT=2.
// 64 windows/batch (128x2 column strips), N=256 tokens/window.
// One CTA per (window, head): 128 threads, TWO query tokens per thread
// (register blocking halves smem traffic per query).
// Head-dim packed in f32x2 pairs -> fma.rn.f32x2 halves FMA-pipe ops.

#define HW (128*128)

typedef unsigned long long u64;

__device__ __forceinline__ u64 pk2(float lo, float hi) {
    u64 r; asm("mov.b64 %0,{%1,%2};" : "=l"(r) : "f"(lo), "f"(hi)); return r;
}
__device__ __forceinline__ void up2(u64 v, float& lo, float& hi) {
    asm("mov.b64 {%0,%1},%2;" : "=f"(lo), "=f"(hi) : "l"(v));
}
__device__ __forceinline__ u64 fma2(u64 a, u64 b, u64 c) {
    u64 d; asm("fma.rn.f32x2 %0,%1,%2,%3;" : "=l"(d) : "l"(a), "l"(b), "l"(c)); return d;
}
__device__ __forceinline__ u64 mul2(u64 a, u64 b) {
    u64 d; asm("mul.rn.f32x2 %0,%1,%2;" : "=l"(d) : "l"(a), "l"(b)); return d;
}
__device__ __forceinline__ u64 add2(u64 a, u64 b) {
    u64 d; asm("add.rn.f32x2 %0,%1,%2;" : "=l"(d) : "l"(a), "l"(b)); return d;
}
__device__ __forceinline__ float ex2a(float x) {
    float r; asm("ex2.approx.f32 %0,%1;" : "=f"(r) : "f"(x)); return r;
}

__global__ __launch_bounds__(128)
void lepe_attn_kernel(const float* __restrict__ temp,
                      const float* __restrict__ conv_w,
                      const float* __restrict__ conv_b,
                      float* __restrict__ out)
{
    const int wcol = blockIdx.x;   // 0..63
    const int b    = blockIdx.y;   // 0..3
    const int head = blockIdx.z;   // 0..7
    const int t    = threadIdx.x;  // 0..127

    __shared__ __align__(16) float Ks[256][8];
    __shared__ __align__(16) float Vs[256][8];
    __shared__ float wsh[8][9];
    __shared__ float bsh[8];

    const int c0 = head * 8;
    const int w0 = 2 * wcol;

    // This thread's two query tokens: n0 = t, n1 = t + 128.
    const int n0 = t,        n1 = t + 128;
    const int h0 = n0 >> 1,  j0 = n0 & 1;
    const int h1 = n1 >> 1,  j1 = n1 & 1;

    const size_t planeQ = ((size_t)(b * 3 + 0) * 64 + c0) * HW;
    const size_t planeK = ((size_t)(b * 3 + 1) * 64 + c0) * HW;
    const size_t planeV = ((size_t)(b * 3 + 2) * 64 + c0) * HW;
    const size_t off0 = (size_t)h0 * 128 + w0 + j0;
    const size_t off1 = (size_t)h1 * 128 + w0 + j1;

    // Stage K, V (two token rows per thread), high MLP.
#pragma unroll
    for (int d = 0; d < 8; ++d) {
        Ks[n0][d] = temp[planeK + (size_t)d * HW + off0];
        Ks[n1][d] = temp[planeK + (size_t)d * HW + off1];
        Vs[n0][d] = temp[planeV + (size_t)d * HW + off0];
        Vs[n1][d] = temp[planeV + (size_t)d * HW + off1];
    }
    if (t < 72) { int d = t / 9, i = t % 9; wsh[d][i] = conv_w[(c0 + d) * 9 + i]; }
    if (t < 8)  bsh[t] = conv_b[c0 + t];

    // Q rows in packed pairs, scale (hd^-0.5) * log2(e) folded in.
    const float sc = 0.35355339059327373f * 1.4426950408889634f;
    u64 q0[4], q1[4];
#pragma unroll
    for (int p = 0; p < 4; ++p) {
        q0[p] = pk2(temp[planeQ + (size_t)(2 * p) * HW + off0] * sc,
                    temp[planeQ + (size_t)(2 * p + 1) * HW + off0] * sc);
        q1[p] = pk2(temp[planeQ + (size_t)(2 * p) * HW + off1] * sc,
                    temp[planeQ + (size_t)(2 * p + 1) * HW + off1] * sc);
    }
    __syncthreads();

    u64 o[2][4] = {{0ull,0ull,0ull,0ull},{0ull,0ull,0ull,0ull}};
    u64 l2 = 0ull;   // (l for q0, l for q1)

#pragma unroll 4
    for (int m = 0; m < 256; ++m) {
        const ulonglong2 kA = ((const ulonglong2*)Ks[m])[0]; // (k0,k1),(k2,k3)
        const ulonglong2 kB = ((const ulonglong2*)Ks[m])[1]; // (k4,k5),(k6,k7)

        u64 sa = mul2(q0[0], kA.x);
        sa = fma2(q0[1], kA.y, sa);
        sa = fma2(q0[2], kB.x, sa);
        sa = fma2(q0[3], kB.y, sa);
        u64 sb = mul2(q1[0], kA.x);
        sb = fma2(q1[1], kA.y, sb);
        sb = fma2(q1[2], kB.x, sb);
        sb = fma2(q1[3], kB.y, sb);

        float aL, aH, bL, bH;
        up2(sa, aL, aH);
        up2(sb, bL, bH);
        const float pa = ex2a(fminf(aL + aH, 100.f));
        const float pb = ex2a(fminf(bL + bH, 100.f));
        l2 = add2(l2, pk2(pa, pb));

        const u64 paa = pk2(pa, pa);
        const u64 pbb = pk2(pb, pb);
        const ulonglong2 vA = ((const ulonglong2*)Vs[m])[0];
        const ulonglong2 vB = ((const ulonglong2*)Vs[m])[1];
        o[0][0] = fma2(vA.x, paa, o[0][0]);
        o[0][1] = fma2(vA.y, paa, o[0][1]);
        o[0][2] = fma2(vB.x, paa, o[0][2]);
        o[0][3] = fma2(vB.y, paa, o[0][3]);
        o[1][0] = fma2(vA.x, pbb, o[1][0]);
        o[1][1] = fma2(vA.y, pbb, o[1][1]);
        o[1][2] = fma2(vB.x, pbb, o[1][2]);
        o[1][3] = fma2(vB.y, pbb, o[1][3]);
    }

    float lA, lB;
    up2(l2, lA, lB);
    const float invs[2] = {1.f / lA, 1.f / lB};
    const int   hs[2]   = {h0, h1};
    const int   js[2]   = {j0, j1};

#pragma unroll
    for (int qi = 0; qi < 2; ++qi) {
        const int h = hs[qi], j = js[qi];
        const float inv = invs[qi];

        // LePE: depthwise 3x3 conv on V within the 128x2 window.
        float r[8];
#pragma unroll
        for (int d = 0; d < 8; ++d) r[d] = bsh[d];
#pragma unroll
        for (int dy = -1; dy <= 1; ++dy) {
            const int hh = h + dy;
            if (hh < 0 || hh >= 128) continue;
#pragma unroll
            for (int dx = -1; dx <= 1; ++dx) {
                const int jj = j + dx;
                if (jj < 0 || jj > 1) continue;
                const int mm = hh * 2 + jj;
                const int wi = (dy + 1) * 3 + (dx + 1);
#pragma unroll
                for (int d = 0; d < 8; ++d) r[d] += Vs[mm][d] * wsh[d][wi];
            }
        }

        const size_t oidx = ((size_t)b * HW + (size_t)h * 128 + w0 + j) * 64 + c0;
        float x0, x1;
        float4 A, B;
        up2(o[qi][0], x0, x1); A.x = x0 * inv + r[0]; A.y = x1 * inv + r[1];
        up2(o[qi][1], x0, x1); A.z = x0 * inv + r[2]; A.w = x1 * inv + r[3];
        up2(o[qi][2], x0, x1); B.x = x0 * inv + r[4]; B.y = x1 * inv + r[5];
        up2(o[qi][3], x0, x1); B.z = x0 * inv + r[6]; B.w = x1 * inv + r[7];
        *(float4*)&out[oidx]     = A;
        *(float4*)&out[oidx + 4] = B;
    }
}

extern "C" void kernel_launch(void* const* d_in, const int* in_sizes, int n_in,
                              void* d_out, int out_size)
{
    const float* temp   = (const float*)d_in[0];
    const float* conv_w = (const float*)d_in[1];
    const float* conv_b = (const float*)d_in[2];
    float* out          = (float*)d_out;

    dim3 grid(64, 4, 8);   // (wcol, batch, head)
    dim3 block(128);
    lepe_attn_kernel<<<grid, block>>>(temp, conv_w, conv_b, out);
}

// round 5
// speedup vs baseline: 2.0723x; 1.4620x over previous
#include <cuda_runtime.h>

// LePE CSWin attention via tf32 tensor cores (mma.sync.m16n8k8).
// B=4, C=64, H=W=128, heads=8, hd=8, SPLIT=2 -> 2048 (window,head) problems
// of N=256 tokens, d=8. One CTA (128 thr, 4 warps) per problem; warp w owns
// query rows [64w, 64w+64). Keys streamed in chunks of 16.
// S = Q@K^T (1 k-tile: hd=8), P = exp2(S) unnormalized, O += P@V,
// rowsums tracked per-thread, LePE 3x3 depthwise conv added in exact fp32.

#define HW (128*128)

typedef unsigned u32;

__device__ __forceinline__ u32 cvt_tf32(float x){
    u32 r; asm("cvt.rna.tf32.f32 %0,%1;" : "=r"(r) : "f"(x)); return r;
}
__device__ __forceinline__ float ex2a(float x){
    float r; asm("ex2.approx.f32 %0,%1;" : "=f"(r) : "f"(x)); return r;
}
__device__ __forceinline__ float rcpa(float x){
    float r; asm("rcp.approx.f32 %0,%1;" : "=f"(r) : "f"(x)); return r;
}
__device__ __forceinline__ void mma_tf32(float d[4], const u32 a[4], const u32 b[2],
                                         const float c[4]){
    asm("mma.sync.aligned.m16n8k8.row.col.f32.tf32.tf32.f32 "
        "{%0,%1,%2,%3},{%4,%5,%6,%7},{%8,%9},{%10,%11,%12,%13};"
        : "=f"(d[0]),"=f"(d[1]),"=f"(d[2]),"=f"(d[3])
        : "r"(a[0]),"r"(a[1]),"r"(a[2]),"r"(a[3]),
          "r"(b[0]),"r"(b[1]),
          "f"(c[0]),"f"(c[1]),"f"(c[2]),"f"(c[3]));
}

#define KSTR 12   // K smem row stride (floats): conflict-free for B-frag pattern

__global__ __launch_bounds__(128)
void lepe_attn_tc(const float* __restrict__ temp,
                  const float* __restrict__ conv_w,
                  const float* __restrict__ conv_b,
                  float* __restrict__ out)
{
    const int wcol = blockIdx.x;   // 0..63
    const int b    = blockIdx.y;   // 0..3
    const int head = blockIdx.z;   // 0..7
    const int t    = threadIdx.x;
    const int warp = t >> 5;
    const int lane = t & 31;
    const int g    = lane >> 2;    // group 0..7
    const int tg   = lane & 3;     // thread-in-group

    __shared__ __align__(16) float Ks[256 * KSTR];
    __shared__ __align__(16) float Vs[256 * 8];
    __shared__ float wsh[72];
    __shared__ float bsh[8];

    const int c0 = head * 8;
    const int w0 = 2 * wcol;

    const size_t planeQ = ((size_t)(b*3 + 0) * 64 + c0) * HW;
    const size_t planeK = ((size_t)(b*3 + 1) * 64 + c0) * HW;
    const size_t planeV = ((size_t)(b*3 + 2) * 64 + c0) * HW;

    // ---- stage K, V (exact fp32) into smem; 2 token rows per thread ----
#pragma unroll
    for (int s = 0; s < 2; ++s) {
        const int n   = t + 128 * s;
        const size_t off = (size_t)((n >> 1) << 7) + w0 + (n & 1);
        float kv[8], vv[8];
#pragma unroll
        for (int d = 0; d < 8; ++d) {
            kv[d] = temp[planeK + (size_t)d * HW + off];
            vv[d] = temp[planeV + (size_t)d * HW + off];
        }
        *(float4*)&Ks[n*KSTR    ] = make_float4(kv[0],kv[1],kv[2],kv[3]);
        *(float4*)&Ks[n*KSTR + 4] = make_float4(kv[4],kv[5],kv[6],kv[7]);
        *(float4*)&Vs[n*8    ] = make_float4(vv[0],vv[1],vv[2],vv[3]);
        *(float4*)&Vs[n*8 + 4] = make_float4(vv[4],vv[5],vv[6],vv[7]);
    }
    if (t < 72) wsh[t] = conv_w[c0*9 + t];
    if (t < 8)  bsh[t] = conv_b[c0 + t];

    // ---- Q fragments (scale * log2e folded), persistent in registers ----
    const float sc = 0.35355339059327373f * 1.4426950408889634f;
    u32 aq[4][4];
#pragma unroll
    for (int mi = 0; mi < 4; ++mi) {
        const int n0 = 64*warp + mi*16 + g;
        const int n1 = n0 + 8;
        const size_t o0 = (size_t)((n0 >> 1) << 7) + w0 + (n0 & 1);
        const size_t o1 = (size_t)((n1 >> 1) << 7) + w0 + (n1 & 1);
        aq[mi][0] = cvt_tf32(temp[planeQ + (size_t)(tg  )*HW + o0] * sc);
        aq[mi][1] = cvt_tf32(temp[planeQ + (size_t)(tg  )*HW + o1] * sc);
        aq[mi][2] = cvt_tf32(temp[planeQ + (size_t)(tg+4)*HW + o0] * sc);
        aq[mi][3] = cvt_tf32(temp[planeQ + (size_t)(tg+4)*HW + o1] * sc);
    }
    __syncthreads();

    float O[4][4];
#pragma unroll
    for (int mi = 0; mi < 4; ++mi)
#pragma unroll
        for (int i = 0; i < 4; ++i) O[mi][i] = 0.f;
    float rs[8];
#pragma unroll
    for (int i = 0; i < 8; ++i) rs[i] = 0.f;

    const int srcA = (lane & ~3) + (tg >> 1);
    const int srcB = srcA + 2;
    const bool odd = tg & 1;

    // ---- main loop: 16 chunks of 16 keys ----
#pragma unroll 1
    for (int ch = 0; ch < 16; ++ch) {
        const int key0 = ch * 16;

        // K B-fragments: b0 = K[key0+ni*8+g][tg], b1 = [..][tg+4]
        u32 bk[2][2];
#pragma unroll
        for (int ni = 0; ni < 2; ++ni) {
            const int row = key0 + ni*8 + g;
            bk[ni][0] = cvt_tf32(Ks[row*KSTR + tg]);
            bk[ni][1] = cvt_tf32(Ks[row*KSTR + tg + 4]);
        }

        // S tiles: acc[mi][ni][4]
        float acc[4][2][4];
        const float zero[4] = {0.f,0.f,0.f,0.f};
#pragma unroll
        for (int mi = 0; mi < 4; ++mi)
#pragma unroll
            for (int ni = 0; ni < 2; ++ni)
                mma_tf32(acc[mi][ni], aq[mi], bk[ni], zero);

        // exp2 + rowsums (pre-shuffle layout: rows g / g+8 of tile mi)
#pragma unroll
        for (int mi = 0; mi < 4; ++mi)
#pragma unroll
            for (int ni = 0; ni < 2; ++ni) {
                float* p = acc[mi][ni];
                p[0] = ex2a(p[0]); p[1] = ex2a(p[1]);
                p[2] = ex2a(p[2]); p[3] = ex2a(p[3]);
                rs[2*mi  ] += p[0] + p[1];
                rs[2*mi+1] += p[2] + p[3];
            }

        // PV: for each k-tile (=ni), load V B-frag, convert P tile, mma
#pragma unroll
        for (int ki = 0; ki < 2; ++ki) {
            u32 bv[2];
            bv[0] = cvt_tf32(Vs[(key0 + ki*8 + tg  )*8 + g]);
            bv[1] = cvt_tf32(Vs[(key0 + ki*8 + tg+4)*8 + g]);
#pragma unroll
            for (int mi = 0; mi < 4; ++mi) {
                const float* p = acc[mi][ki];
                // accumulator layout -> A-operand layout (8 shfl + 4 sel)
                float e0 = __shfl_sync(0xffffffffu, p[0], srcA);
                float e1 = __shfl_sync(0xffffffffu, p[1], srcA);
                float f0 = __shfl_sync(0xffffffffu, p[2], srcA);
                float f1 = __shfl_sync(0xffffffffu, p[3], srcA);
                float h0 = __shfl_sync(0xffffffffu, p[0], srcB);
                float h1 = __shfl_sync(0xffffffffu, p[1], srcB);
                float i0 = __shfl_sync(0xffffffffu, p[2], srcB);
                float i1 = __shfl_sync(0xffffffffu, p[3], srcB);
                u32 ap[4];
                ap[0] = cvt_tf32(odd ? e1 : e0);
                ap[1] = cvt_tf32(odd ? f1 : f0);
                ap[2] = cvt_tf32(odd ? h1 : h0);
                ap[3] = cvt_tf32(odd ? i1 : i0);
                mma_tf32(O[mi], ap, bv, O[mi]);
            }
        }
    }

    // ---- rowsum reduction across the 4-thread group ----
#pragma unroll
    for (int i = 0; i < 8; ++i) {
        rs[i] += __shfl_xor_sync(0xffffffffu, rs[i], 1);
        rs[i] += __shfl_xor_sync(0xffffffffu, rs[i], 2);
    }

    // ---- epilogue: normalize, LePE conv (exact fp32), store ----
    const int d0 = 2*tg;
#pragma unroll
    for (int mi = 0; mi < 4; ++mi) {
#pragma unroll
        for (int half = 0; half < 2; ++half) {
            const int q = 64*warp + mi*16 + g + 8*half;
            const int h = q >> 1, j = q & 1;
            const float inv = rcpa(rs[2*mi + half]);
            float r0 = bsh[d0], r1 = bsh[d0+1];
#pragma unroll
            for (int dy = -1; dy <= 1; ++dy) {
                const int hh = h + dy;
                if (hh < 0 || hh >= 128) continue;
#pragma unroll
                for (int jj = 0; jj <= 1; ++jj) {
                    const int wi = (dy+1)*3 + (jj - j + 1);
                    const float2 v = *(const float2*)&Vs[(hh*2 + jj)*8 + d0];
                    r0 += v.x * wsh[d0*9 + wi];
                    r1 += v.y * wsh[(d0+1)*9 + wi];
                }
            }
            const float oa = O[mi][2*half    ] * inv + r0;
            const float ob = O[mi][2*half + 1] * inv + r1;
            const size_t oidx = ((size_t)b*HW + (size_t)h*128 + w0 + j)*64 + c0 + d0;
            *(float2*)&out[oidx] = make_float2(oa, ob);
        }
    }
}

extern "C" void kernel_launch(void* const* d_in, const int* in_sizes, int n_in,
                              void* d_out, int out_size)
{
    const float* temp   = (const float*)d_in[0];
    const float* conv_w = (const float*)d_in[1];
    const float* conv_b = (const float*)d_in[2];
    float* out          = (float*)d_out;

    dim3 grid(64, 4, 8);   // (wcol, batch, head)
    dim3 block(128);
    lepe_attn_tc<<<grid, block>>>(temp, conv_w, conv_b, out);
}